// round 4
// baseline (speedup 1.0000x reference)
#include <cuda_runtime.h>

// AdaptiveSample, channel-interleaved smem (LDS.128 serves 4 channels per tap):
//   weights: softmax over 15 sampled taps of valid*posw*guide (per pixel)
//   out[b,c,h,w] = sum_s wv[s] * feat[b,c,h+dy_s,w+dx_s]  (zero-pad via masked weights)
//   second output = passthrough copy of features.

namespace {
constexpr int H  = 256;
constexpr int W  = 512;
constexpr int C  = 32;
constexpr int S  = 15;
constexpr int KS = 5;
constexpr int KK = 25;
constexpr int HW = H * W;

constexpr int BW = 32;            // tile width (warp-coalesced)
constexpr int BH = 8;             // tile height
constexpr int NT = BW * BH;       // 256 threads

constexpr int FP    = 48;         // smem pitch (floats/pixels per row): cols [w0-8, w0+40)
constexpr int FR    = 12;         // smem rows: [h0-2, h0+10)
constexpr int NPIX  = FP * FR;    // 576 pixels per tile
constexpr int SLOTQ = NPIX * 4;   // floats per 4-channel quad buffer (2304)
constexpr int PC    = 16;         // channels per phase (4 quads)
constexpr int NP    = C / PC;     // 2 phases
constexpr int GBUF  = BH * BW * KK;  // guide tile floats (6400) fits in 4*SLOTQ=9216
}

__global__ __launch_bounds__(NT, 4)
void adaptive_sample_kernel(const float* __restrict__ depth,
                            const float* __restrict__ features,
                            const float* __restrict__ guide,
                            const int*   __restrict__ sidx,
                            float* __restrict__ out,
                            float* __restrict__ outf,
                            int do_copy)
{
    __shared__ float       shbuf[4 * SLOTQ];   // 9216 floats = 36 KB
    __shared__ float       sh_posw[S];
    __shared__ int         sh_k[S];
    __shared__ signed char sh_dy[S], sh_dx[S];

    const int tx  = threadIdx.x;
    const int ty  = threadIdx.y;
    const int tid = ty * BW + tx;
    const int w0  = blockIdx.x * BW;
    const int h0  = blockIdx.y * BH;
    const int b   = blockIdx.z;

    // ---- tap metadata (one thread; S=15 trivial) ----
    if (tid == 0) {
        float pw[S];
        float sum = 0.f;
        #pragma unroll
        for (int s = 0; s < S; ++s) {
            int k  = sidx[s];
            int px = k % KS;
            int py = k / KS;
            float fx = (float)px - 2.f;
            float fy = (float)py - 2.f;
            float v  = __expf(-0.5f * sqrtf(fx * fx + fy * fy));
            pw[s] = v; sum += v;
            sh_k[s]  = k;
            sh_dy[s] = (signed char)(py - 2);
            sh_dx[s] = (signed char)(px - 2);
        }
        float inv = 1.f / sum;
        #pragma unroll
        for (int s = 0; s < S; ++s) sh_posw[s] = pw[s] * inv;
    }

    // ---- stage guide tile into shbuf (contiguous float4 rows) ----
    #pragma unroll
    for (int it = 0; it < (GBUF / 4 + NT - 1) / NT; ++it) {
        int i4 = tid + it * NT;
        if (i4 < GBUF / 4) {
            int row = i4 / (BW * KK / 4);
            int in4 = i4 - row * (BW * KK / 4);
            const float4* src = reinterpret_cast<const float4*>(
                guide + (((size_t)b * H + (h0 + row)) * W + w0) * KK) + in4;
            reinterpret_cast<float4*>(shbuf + row * BW * KK)[in4] = *src;
        }
    }
    __syncthreads();

    const int h = h0 + ty;
    const int w = w0 + tx;

    // ---- per-pixel softmax weights + smem tap pixel-offsets ----
    const float* drow = depth + (size_t)b * HW;
    const float* gpix = shbuf + (ty * BW + tx) * KK;   // lane stride 25: conflict-free

    float wv[S];
    int   toff[S];                 // pixel index into tile (float4 index into quad buf)
    unsigned ibm  = 0u;
    float    gmax = 0.f;           // logits >= 0
    #pragma unroll
    for (int s = 0; s < S; ++s) {
        int dy = (int)sh_dy[s], dx = (int)sh_dx[s];
        int hh = h + dy, ww = w + dx;
        bool ib = ((unsigned)hh < (unsigned)H) && ((unsigned)ww < (unsigned)W);
        float d = ib ? __ldg(drow + hh * W + ww) : 0.f;
        bool valid = ib && (d > 0.f) && (d < 192.0f);
        float logit = valid ? sh_posw[s] * gpix[sh_k[s]] : 0.f;
        wv[s] = logit;
        gmax  = fmaxf(gmax, logit);
        ibm  |= (unsigned)ib << s;
        toff[s] = (ty + 2 + dy) * FP + (tx + 8 + dx);
    }
    float esum = 0.f;
    #pragma unroll
    for (int s = 0; s < S; ++s) { wv[s] = __expf(wv[s] - gmax); esum += wv[s]; }
    float inv = 1.f / esum;
    #pragma unroll
    for (int s = 0; s < S; ++s)
        wv[s] = ((ibm >> s) & 1u) ? wv[s] * inv : 0.f;  // OOB tap == zero-padded feature

    __syncthreads();  // guide reads done; shbuf becomes feature buffer

    const float* fbase  = features + (size_t)b * C * HW;
    const size_t pix    = (size_t)h * W + w;
    float*       obase  = out  + (size_t)b * C * HW + pix;

    #pragma unroll
    for (int ph = 0; ph < NP; ++ph) {
        const int c0 = ph * PC;

        // ---- stage 16 channels, channel-interleaved: per unit = 1 pixel of one
        //      quad -> 4 coalesced scalar LDG + 1 STS.128. 2304 units / 256 thr = 9 it.
        #pragma unroll
        for (int it = 0; it < (4 * NPIX) / NT; ++it) {
            int u   = tid + it * NT;
            int q   = u / NPIX;
            int p   = u - q * NPIX;
            int r   = p / FP;
            int col = p - r * FP;
            int gh  = min(max(h0 + r - 2, 0), H - 1);
            int gw  = min(max(w0 - 8 + col, 0), W - 1);
            const float* src = fbase + (size_t)(c0 + q * 4) * HW + gh * W + gw;
            float4 v;
            v.x = __ldg(src);
            v.y = __ldg(src + HW);
            v.z = __ldg(src + 2 * HW);
            v.w = __ldg(src + 3 * HW);
            reinterpret_cast<float4*>(shbuf)[q * NPIX + p] = v;
        }
        __syncthreads();

        // ---- compute: per quad, 15 x (LDS.128 + 4 FFMA) ----
        #pragma unroll
        for (int q = 0; q < 4; ++q) {
            const float4* bq = reinterpret_cast<const float4*>(shbuf) + q * NPIX;
            float a0 = 0.f, a1 = 0.f, a2 = 0.f, a3 = 0.f;
            #pragma unroll
            for (int s = 0; s < S; ++s) {
                float4 v = bq[toff[s]];
                float wt = wv[s];
                a0 = fmaf(wt, v.x, a0);
                a1 = fmaf(wt, v.y, a1);
                a2 = fmaf(wt, v.z, a2);
                a3 = fmaf(wt, v.w, a3);
            }
            obase[(size_t)(c0 + q * 4 + 0) * HW] = a0;
            obase[(size_t)(c0 + q * 4 + 1) * HW] = a1;
            obase[(size_t)(c0 + q * 4 + 2) * HW] = a2;
            obase[(size_t)(c0 + q * 4 + 3) * HW] = a3;
        }
        __syncthreads();
    }

    // ---- passthrough copy, global->global float4 (tile is L2-hot) ----
    if (do_copy) {
        float* ocbase = outf + (size_t)b * C * HW;
        #pragma unroll
        for (int it = 0; it < (C * BH * BW / 4) / NT; ++it) {   // 2048/256 = 8
            int i   = tid + it * NT;
            int c   = i >> 6;             // / 64
            int rem = i & 63;
            int r   = rem >> 3;
            int q4  = rem & 7;
            size_t off = (size_t)c * HW + (size_t)(h0 + r) * W + w0 + q4 * 4;
            float4 v = __ldg(reinterpret_cast<const float4*>(fbase + off));
            *reinterpret_cast<float4*>(ocbase + off) = v;
        }
    }
}

extern "C" void kernel_launch(void* const* d_in, const int* in_sizes, int n_in,
                              void* d_out, int out_size)
{
    const float* depth    = (const float*)d_in[0];
    const float* features = (const float*)d_in[1];
    const float* guide    = (const float*)d_in[2];
    const int*   sidx     = (const int*)d_in[3];

    float* out = (float*)d_out;
    const int featN = in_sizes[1];                       // B*C*H*W
    const int do_copy = (out_size >= 2 * featN) ? 1 : 0; // tuple output: (out, features)
    float* outf = out + featN;

    dim3 block(BW, BH);
    dim3 grid(W / BW, H / BH, 2 /*B*/);
    adaptive_sample_kernel<<<grid, block>>>(depth, features, guide, sidx,
                                            out, outf, do_copy);
}